// round 1
// baseline (speedup 1.0000x reference)
#include <cuda_runtime.h>
#include <cstdint>

#define BATCH 64
#define NOBJ 64
#define HID 256
#define NOUT 28
#define QD 128
#define KC 32   // K-chunk for weight staging

// Scratch (allocation-free rule: __device__ globals)
__device__ float g_Abuf[BATCH * NOBJ * HID];     // xf @ g1_w[0:26]
__device__ float g_Bbuf[BATCH * NOBJ * HID];     // xf @ g1_w[26:52] + qst @ g1_w[52:180] + g1_b
__device__ float g_partial[BATCH * NOBJ * HID];  // sum_j h4 for each (b, i)

// ---------------------------------------------------------------------------
// Helpers: packed f32x2 FMA (sm_103a dual-rate fp32 path), cp.async
// ---------------------------------------------------------------------------
__device__ __forceinline__ void cp_async16(void* dst, const void* src) {
    unsigned d = (unsigned)__cvta_generic_to_shared(dst);
    asm volatile("cp.async.cg.shared.global [%0], [%1], 16;" :: "r"(d), "l"(src));
}
__device__ __forceinline__ void cp_commit() { asm volatile("cp.async.commit_group;"); }
__device__ __forceinline__ void cp_wait_all() { asm volatile("cp.async.wait_group 0;" ::: "memory"); }

__device__ __forceinline__ unsigned long long pack2(float a) {
    unsigned long long r;
    asm("mov.b64 %0, {%1, %1};" : "=l"(r) : "f"(a));
    return r;
}
__device__ __forceinline__ void fma2(unsigned long long& acc, unsigned long long a, unsigned long long b) {
    asm("fma.rn.f32x2 %0, %1, %2, %0;" : "+l"(acc) : "l"(a), "l"(b));
}
__device__ __forceinline__ float2 unpack2(unsigned long long v) {
    float2 f;
    asm("mov.b64 {%0, %1}, %2;" : "=f"(f.x), "=f"(f.y) : "l"(v));
    return f;
}

// ---------------------------------------------------------------------------
// Prep: split first g-layer into per-object A and B halves.
// A[b][j][h] = sum_c xf[b][j][c]   * g1_w[c][h]         (c in 0..25)
// B[b][i][h] = sum_c xf[b][i][c]   * g1_w[26+c][h]      (c in 0..25)
//            + sum_c qst[b][c]     * g1_w[52+c][h] + g1_b[h]
// ---------------------------------------------------------------------------
__global__ void prep_kernel(const float* __restrict__ x, const float* __restrict__ qst,
                            const float* __restrict__ g1w, const float* __restrict__ g1b)
{
    __shared__ float sxf[NOBJ * 26];
    __shared__ float sq[QD];
    int b = blockIdx.x, tid = threadIdx.x;

    for (int t = tid; t < NOBJ * 26; t += 256) {
        int j = t / 26, c = t % 26;
        float v;
        if (c < 24)       v = x[(b * 24 + c) * 64 + j];
        else if (c == 24) v = ((float)j * 0.125f - 4.0f) * 0.25f;  // (a/d - d/2)/(d/2), float division
        else              v = ((float)(j & 7) - 4.0f) * 0.25f;     // (a%d - d/2)/(d/2)
        sxf[t] = v;
    }
    if (tid < QD) sq[tid] = qst[b * QD + tid];
    __syncthreads();

    int h = tid;  // 256 threads = 256 hidden units
    // ---- pass A ----
    {
        float acc[NOBJ];
        #pragma unroll
        for (int j = 0; j < NOBJ; j++) acc[j] = 0.f;
        for (int c = 0; c < 26; c++) {
            float w = g1w[c * HID + h];
            #pragma unroll
            for (int j = 0; j < NOBJ; j++) acc[j] += sxf[j * 26 + c] * w;
        }
        for (int j = 0; j < NOBJ; j++) g_Abuf[(b * NOBJ + j) * HID + h] = acc[j];
    }
    // ---- pass B ----
    {
        float qdot = g1b[h];
        for (int c = 0; c < QD; c++) qdot += sq[c] * g1w[(52 + c) * HID + h];
        float acc[NOBJ];
        #pragma unroll
        for (int j = 0; j < NOBJ; j++) acc[j] = 0.f;
        for (int c = 0; c < 26; c++) {
            float w = g1w[(26 + c) * HID + h];
            #pragma unroll
            for (int j = 0; j < NOBJ; j++) acc[j] += sxf[j * 26 + c] * w;
        }
        for (int j = 0; j < NOBJ; j++) g_Bbuf[(b * NOBJ + j) * HID + h] = acc[j] + qdot;
    }
}

// ---------------------------------------------------------------------------
// Fused g-MLP layers 2..4 over a 64-row pair tile (fixed b, i; all j).
// Register-tiled GEMM: 256 threads, each thread owns an 8(m) x 8(n) tile held
// as 8x4 packed f32x2 accumulators. Weights stream HBM->smem via cp.async,
// double-buffered in K=32 chunks. h ping-pongs between two smem buffers.
// ---------------------------------------------------------------------------
template <bool FINAL>
__device__ __noinline__ void gemm_layer(const float* __restrict__ hSrc,
                                        float* __restrict__ hDst,
                                        float* __restrict__ Wbuf,
                                        const float* __restrict__ Wg,
                                        const float* __restrict__ bias,
                                        float* __restrict__ outPtr)
{
    int tid = threadIdx.x;
    int tm = tid >> 5;   // 0..7  -> rows tm*8 .. tm*8+7
    int tn = tid & 31;   // 0..31 -> cols tn*8 .. tn*8+7

    unsigned long long acc[8][4];
    #pragma unroll
    for (int r = 0; r < 8; r++)
        #pragma unroll
        for (int p = 0; p < 4; p++) acc[r][p] = 0ull;

    // preload chunk 0
    {
        const float4* src = (const float4*)Wg;
        float4* dst = (float4*)Wbuf;
        #pragma unroll
        for (int q = 0; q < 8; q++) cp_async16(dst + tid + 256 * q, src + tid + 256 * q);
        cp_commit();
    }

    #pragma unroll 1
    for (int ch = 0; ch < HID / KC; ch++) {
        cp_wait_all();
        __syncthreads();   // chunk ch ready; all warps done with chunk ch-1's buffer
        if (ch < HID / KC - 1) {
            const float4* src = (const float4*)(Wg + (ch + 1) * KC * HID);
            float4* dst = (float4*)(Wbuf + ((ch + 1) & 1) * KC * HID);
            #pragma unroll
            for (int q = 0; q < 8; q++) cp_async16(dst + tid + 256 * q, src + tid + 256 * q);
            cp_commit();
        }
        const float* Wc = Wbuf + (ch & 1) * KC * HID;
        const float* aBase = hSrc + tm * 8 * HID + ch * KC;
        #pragma unroll
        for (int kk = 0; kk < KC; kk++) {
            unsigned long long apk[8];
            #pragma unroll
            for (int r = 0; r < 8; r++) apk[r] = pack2(aBase[r * HID + kk]);  // smem broadcast
            const ulonglong2* bp = (const ulonglong2*)(Wc + kk * HID + tn * 8);
            ulonglong2 b01 = bp[0];
            ulonglong2 b23 = bp[1];
            unsigned long long bb[4] = {b01.x, b01.y, b23.x, b23.y};
            #pragma unroll
            for (int r = 0; r < 8; r++)
                #pragma unroll
                for (int p = 0; p < 4; p++) fma2(acc[r][p], apk[r], bb[p]);
        }
    }

    float bv[8];
    #pragma unroll
    for (int c = 0; c < 8; c++) bv[c] = bias[tn * 8 + c];

    if (!FINAL) {
        #pragma unroll
        for (int r = 0; r < 8; r++) {
            float o[8];
            #pragma unroll
            for (int p = 0; p < 4; p++) {
                float2 v = unpack2(acc[r][p]);
                o[2 * p]     = fmaxf(v.x + bv[2 * p], 0.f);
                o[2 * p + 1] = fmaxf(v.y + bv[2 * p + 1], 0.f);
            }
            float* drow = hDst + (tm * 8 + r) * HID + tn * 8;
            float4 q0 = {o[0], o[1], o[2], o[3]};
            float4 q1 = {o[4], o[5], o[6], o[7]};
            ((float4*)drow)[0] = q0;
            ((float4*)drow)[1] = q1;
        }
    } else {
        // relu(acc + bias), then deterministic sum over the 64 rows of the tile
        float cs[8];
        #pragma unroll
        for (int c = 0; c < 8; c++) cs[c] = 0.f;
        #pragma unroll
        for (int r = 0; r < 8; r++) {
            #pragma unroll
            for (int p = 0; p < 4; p++) {
                float2 v = unpack2(acc[r][p]);
                cs[2 * p]     += fmaxf(v.x + bv[2 * p], 0.f);
                cs[2 * p + 1] += fmaxf(v.y + bv[2 * p + 1], 0.f);
            }
        }
        #pragma unroll
        for (int c = 0; c < 8; c++) hDst[tm * HID + tn * 8 + c] = cs[c];  // 8x256 scratch
        __syncthreads();
        float s = 0.f;
        #pragma unroll
        for (int t = 0; t < 8; t++) s += hDst[t * HID + tid];
        outPtr[tid] = s;
    }
}

__global__ __launch_bounds__(256, 1)
void rn_main_kernel(const float* __restrict__ g2w, const float* __restrict__ g2b,
                    const float* __restrict__ g3w, const float* __restrict__ g3b,
                    const float* __restrict__ g4w, const float* __restrict__ g4b)
{
    extern __shared__ float smem[];
    float* hA = smem;                       // 64 x 256
    float* hB = smem + NOBJ * HID;          // 64 x 256
    float* Wbuf = smem + 2 * NOBJ * HID;    // 2 x 32 x 256

    int i = blockIdx.x, b = blockIdx.y, tid = threadIdx.x;

    // Layer 1: h1[j][h] = relu(A[b][j][h] + B[b][i][h])
    const float4* Ag = (const float4*)(g_Abuf + (size_t)b * NOBJ * HID);
    const float4* Bg = (const float4*)(g_Bbuf + ((size_t)b * NOBJ + i) * HID);
    for (int v = tid; v < NOBJ * HID / 4; v += 256) {
        int h4 = v & 63;
        float4 a = Ag[v];
        float4 bb = Bg[h4];
        float4 r;
        r.x = fmaxf(a.x + bb.x, 0.f);
        r.y = fmaxf(a.y + bb.y, 0.f);
        r.z = fmaxf(a.z + bb.z, 0.f);
        r.w = fmaxf(a.w + bb.w, 0.f);
        ((float4*)hA)[v] = r;
    }
    __syncthreads();

    gemm_layer<false>(hA, hB, Wbuf, g2w, g2b, nullptr);
    __syncthreads();
    gemm_layer<false>(hB, hA, Wbuf, g3w, g3b, nullptr);
    __syncthreads();
    gemm_layer<true>(hA, hB, Wbuf, g4w, g4b, g_partial + ((size_t)b * NOBJ + i) * HID);
}

// ---------------------------------------------------------------------------
// Finish: reduce partials over i, run f-MLP, log_softmax. One CTA per batch.
// ---------------------------------------------------------------------------
__global__ void finish_kernel(const float* __restrict__ f1w, const float* __restrict__ f1b,
                              const float* __restrict__ f2w, const float* __restrict__ f2b,
                              const float* __restrict__ f3w, const float* __restrict__ f3b,
                              float* __restrict__ out)
{
    __shared__ float s0[HID], s1[HID], s2[HID];
    __shared__ float sl[NOUT];
    __shared__ float sred[2];
    int b = blockIdx.x, tid = threadIdx.x;

    float s = 0.f;
    const float* pp = g_partial + (size_t)b * NOBJ * HID + tid;
    for (int i2 = 0; i2 < NOBJ; i2++) s += pp[i2 * HID];
    s0[tid] = s;
    __syncthreads();

    float a = f1b[tid];
    for (int k = 0; k < HID; k++) a += s0[k] * f1w[k * HID + tid];
    s1[tid] = fmaxf(a, 0.f);
    __syncthreads();

    a = f2b[tid];
    for (int k = 0; k < HID; k++) a += s1[k] * f2w[k * HID + tid];
    s2[tid] = fmaxf(a, 0.f);
    __syncthreads();

    if (tid < NOUT) {
        float l = f3b[tid];
        for (int k = 0; k < HID; k++) l += s2[k] * f3w[k * NOUT + tid];
        sl[tid] = l;
    }
    __syncthreads();
    if (tid == 0) {
        float m = sl[0];
        for (int o = 1; o < NOUT; o++) m = fmaxf(m, sl[o]);
        float se = 0.f;
        for (int o = 0; o < NOUT; o++) se += expf(sl[o] - m);
        sred[0] = m;
        sred[1] = logf(se);
    }
    __syncthreads();
    if (tid < NOUT) out[b * NOUT + tid] = sl[tid] - sred[0] - sred[1];
}

// ---------------------------------------------------------------------------
extern "C" void kernel_launch(void* const* d_in, const int* in_sizes, int n_in,
                              void* d_out, int out_size)
{
    const float* x   = (const float*)d_in[0];
    const float* qst = (const float*)d_in[1];
    const float* g1w = (const float*)d_in[2];
    const float* g1b = (const float*)d_in[3];
    const float* g2w = (const float*)d_in[4];
    const float* g2b = (const float*)d_in[5];
    const float* g3w = (const float*)d_in[6];
    const float* g3b = (const float*)d_in[7];
    const float* g4w = (const float*)d_in[8];
    const float* g4b = (const float*)d_in[9];
    const float* f1w = (const float*)d_in[10];
    const float* f1b = (const float*)d_in[11];
    const float* f2w = (const float*)d_in[12];
    const float* f2b = (const float*)d_in[13];
    const float* f3w = (const float*)d_in[14];
    const float* f3b = (const float*)d_in[15];
    float* out = (float*)d_out;

    const size_t smem_bytes = (2 * NOBJ * HID + 2 * KC * HID) * sizeof(float);  // 192 KB
    cudaFuncSetAttribute(rn_main_kernel, cudaFuncAttributeMaxDynamicSharedMemorySize,
                         (int)smem_bytes);

    prep_kernel<<<BATCH, 256>>>(x, qst, g1w, g1b);
    rn_main_kernel<<<dim3(NOBJ, BATCH), 256, smem_bytes>>>(g2w, g2b, g3w, g3b, g4w, g4b);
    finish_kernel<<<BATCH, 256>>>(f1w, f1b, f2w, f2b, f3w, f3b, out);
}

// round 3
// speedup vs baseline: 3.2482x; 3.2482x over previous
#include <cuda_runtime.h>
#include <cuda_fp16.h>
#include <cstdint>

#define BATCH 64
#define NOBJ 64
#define HID 256
#define NOUT 28
#define QD 128

// ---------------------------------------------------------------------------
// Device scratch (allocation-free rule: __device__ globals)
// ---------------------------------------------------------------------------
__device__ float g_Abuf[BATCH * NOBJ * HID];     // xf @ g1_w[0:26]
__device__ float g_Bbuf[BATCH * NOBJ * HID];     // xf @ g1_w[26:52] + qst @ g1_w[52:180] + g1_b
__device__ float g_partial[BATCH * NOBJ * HID];  // sum_j h4 for each (b, i)
__device__ __half g_Wfrag[3 * HID * HID];        // g2/g3/g4 weights, mma-fragment order fp16

// ---------------------------------------------------------------------------
// Helpers
// ---------------------------------------------------------------------------
__device__ __forceinline__ uint32_t smem_u32(const void* p) {
    return (uint32_t)__cvta_generic_to_shared(p);
}
__device__ __forceinline__ void cp_async16(void* dst, const void* src) {
    unsigned d = (unsigned)__cvta_generic_to_shared(dst);
    asm volatile("cp.async.cg.shared.global [%0], [%1], 16;" :: "r"(d), "l"(src));
}
__device__ __forceinline__ void cp_commit() { asm volatile("cp.async.commit_group;"); }
#define CP_WAIT(N) asm volatile("cp.async.wait_group %0;" :: "n"(N) : "memory")

__device__ __forceinline__ void mma16816(float c[4], const uint32_t a[4],
                                         uint32_t b0, uint32_t b1) {
    asm volatile(
        "mma.sync.aligned.m16n8k16.row.col.f32.f16.f16.f32 "
        "{%0,%1,%2,%3}, {%4,%5,%6,%7}, {%8,%9}, {%0,%1,%2,%3};"
        : "+f"(c[0]), "+f"(c[1]), "+f"(c[2]), "+f"(c[3])
        : "r"(a[0]), "r"(a[1]), "r"(a[2]), "r"(a[3]), "r"(b0), "r"(b1));
}
__device__ __forceinline__ void lds64(uint32_t& r0, uint32_t& r1, uint32_t addr) {
    asm volatile("ld.shared.v2.b32 {%0,%1}, [%2];" : "=r"(r0), "=r"(r1) : "r"(addr));
}
__device__ __forceinline__ uint32_t packh2(float x, float y) {
    __half2 h = __floats2half2_rn(x, y);
    return *(uint32_t*)&h;
}

// ---------------------------------------------------------------------------
// Prep: split first g-layer (rank structure of the pair concat).
// ---------------------------------------------------------------------------
__global__ void prep_kernel(const float* __restrict__ x, const float* __restrict__ qst,
                            const float* __restrict__ g1w, const float* __restrict__ g1b)
{
    __shared__ float sxf[NOBJ * 26];
    __shared__ float sq[QD];
    int b = blockIdx.x, tid = threadIdx.x;

    for (int t = tid; t < NOBJ * 26; t += 256) {
        int j = t / 26, c = t % 26;
        float v;
        if (c < 24)       v = x[(b * 24 + c) * 64 + j];
        else if (c == 24) v = ((float)j * 0.125f - 4.0f) * 0.25f;
        else              v = ((float)(j & 7) - 4.0f) * 0.25f;
        sxf[t] = v;
    }
    if (tid < QD) sq[tid] = qst[b * QD + tid];
    __syncthreads();

    int h = tid;
    float qdot = g1b[h];
    for (int c = 0; c < QD; c++) qdot += sq[c] * g1w[(52 + c) * HID + h];

    for (int jc = 0; jc < NOBJ; jc += 8) {
        float accA[8], accB[8];
        #pragma unroll
        for (int u = 0; u < 8; u++) { accA[u] = 0.f; accB[u] = 0.f; }
        for (int c = 0; c < 26; c++) {
            float wA = g1w[c * HID + h];
            float wB = g1w[(26 + c) * HID + h];
            #pragma unroll
            for (int u = 0; u < 8; u++) {
                float xv = sxf[(jc + u) * 26 + c];
                accA[u] += xv * wA;
                accB[u] += xv * wB;
            }
        }
        #pragma unroll
        for (int u = 0; u < 8; u++) {
            g_Abuf[((size_t)b * NOBJ + jc + u) * HID + h] = accA[u];
            g_Bbuf[((size_t)b * NOBJ + jc + u) * HID + h] = accB[u] + qdot;
        }
    }
}

// ---------------------------------------------------------------------------
// Weight prep: W[k][n] row-major fp32 -> fragment-order fp16.
// Layout: [layer][nh(2)][kc(16)][ntl(16)][lane(32)][e(4)] halves.
//   lane = (n%8)*4 + ((k%8)>>1);  e = (k&1) + ((k>>3)&1)*2   (within k%16)
// ---------------------------------------------------------------------------
__global__ void weight_prep(const float* __restrict__ w2, const float* __restrict__ w3,
                            const float* __restrict__ w4)
{
    int l = blockIdx.y;
    const float* w = (l == 0) ? w2 : (l == 1 ? w3 : w4);
    int k = blockIdx.x;     // 0..255
    int n = threadIdx.x;    // 0..255
    int kc = k >> 4, kr = k & 15;
    int nh = n >> 7, ntl = (n >> 3) & 15;
    int lane = ((n & 7) << 2) | ((kr & 7) >> 1);
    int e = (kr & 1) + ((kr >> 3) << 1);
    size_t dest = ((((size_t)(l * 2 + nh) * 16 + kc) * 16 + ntl) * 32 + lane) * 4 + e;
    g_Wfrag[dest] = __float2half(w[k * HID + n]);
}

// ---------------------------------------------------------------------------
// Main: fused g2..g4 via mma.sync (HMMA fp16, fp32 accum).
// CTA: 256 thr / 8 warps, M=128 rows (= 2 i-values x 64 j), N=256, K=256.
// Warp w owns rows 16w..16w+15; activations live in registers (C->A identity).
// Weights stream through 2 x 64KB smem ring (6 chunks = 3 layers x 2 N-halves).
// ---------------------------------------------------------------------------
#define CHUNK_BYTES 65536
#define RED_OFF (2 * CHUNK_BYTES)
#define SMEM_BYTES (RED_OFF + 8 * HID * 4)   // 131072 + 8192 = 139264

__device__ __forceinline__ void prefetch_chunk(char* smem, int c, int tid) {
    const float4* src = (const float4*)((const char*)g_Wfrag + (size_t)c * CHUNK_BYTES);
    float4* dst = (float4*)(smem + (c & 1) * CHUNK_BYTES);
    #pragma unroll
    for (int q = 0; q < 16; q++) cp_async16(dst + tid + 256 * q, src + tid + 256 * q);
}

__global__ __launch_bounds__(256, 1)
void rn_mma_kernel(const float* __restrict__ g2b_, const float* __restrict__ g3b_,
                   const float* __restrict__ g4b_)
{
    extern __shared__ char smem[];
    uint32_t sbase = smem_u32(smem);
    float* red = (float*)(smem + RED_OFF);
    int tid = threadIdx.x, wid = tid >> 5, lane = tid & 31;
    int ti = blockIdx.x, b = blockIdx.y;

    prefetch_chunk(smem, 0, tid);
    cp_commit();

    // ---- Layer-1 A fragments: h1 = relu(Abuf[j] + Bbuf[i]) ----
    uint32_t A[16][4];
    {
        int r = (wid << 4) + (lane >> 2);     // 0..127
        int j = r & 63, il = r >> 6;
        const float* A0 = g_Abuf + ((size_t)b * NOBJ + j) * HID;
        const float* Br = g_Bbuf + ((size_t)b * NOBJ + ti * 2 + il) * HID;
        #pragma unroll
        for (int kc = 0; kc < 16; kc++) {
            int k0 = kc * 16 + (lane & 3) * 2;
            #pragma unroll
            for (int hh = 0; hh < 2; hh++) {
                float2 bb = *(const float2*)(Br + k0 + 8 * hh);
                float2 a0 = *(const float2*)(A0 + k0 + 8 * hh);
                float2 a1 = *(const float2*)(A0 + 8 * HID + k0 + 8 * hh);
                A[kc][2 * hh]     = packh2(fmaxf(a0.x + bb.x, 0.f), fmaxf(a0.y + bb.y, 0.f));
                A[kc][2 * hh + 1] = packh2(fmaxf(a1.x + bb.x, 0.f), fmaxf(a1.y + bb.y, 0.f));
            }
        }
    }

    uint32_t An[8][4];   // pending new-A for nh=0 half

    for (int c = 0; c < 6; c++) {
        int l = c >> 1, nh = c & 1;
        if (c < 5) { prefetch_chunk(smem, c + 1, tid); cp_commit(); CP_WAIT(1); }
        else       { CP_WAIT(0); }
        __syncthreads();

        uint32_t wbase = sbase + (uint32_t)(c & 1) * CHUNK_BYTES + lane * 8;

        float C[16][4];
        #pragma unroll
        for (int t = 0; t < 16; t++)
            #pragma unroll
            for (int q = 0; q < 4; q++) C[t][q] = 0.f;

        #pragma unroll 1
        for (int kc = 0; kc < 16; kc++) {
            #pragma unroll
            for (int ntl = 0; ntl < 16; ntl++) {
                uint32_t b0, b1;
                lds64(b0, b1, wbase + (kc * 16 + ntl) * 256);
                mma16816(C[ntl], A[kc], b0, b1);
            }
        }

        const float* bias = (l == 0) ? g2b_ : ((l == 1) ? g3b_ : g4b_);
        if (l < 2) {
            // relu(C + bias) -> fp16 fragments for next layer (C->A layout identity)
            #pragma unroll
            for (int t2 = 0; t2 < 8; t2++) {
                int n0 = (nh * 16 + 2 * t2) * 8 + (lane & 3) * 2;
                float2 b0v = __ldg((const float2*)(bias + n0));
                float2 b1v = __ldg((const float2*)(bias + n0 + 8));
                uint32_t f0 = packh2(fmaxf(C[2 * t2][0] + b0v.x, 0.f),
                                     fmaxf(C[2 * t2][1] + b0v.y, 0.f));
                uint32_t f1 = packh2(fmaxf(C[2 * t2][2] + b0v.x, 0.f),
                                     fmaxf(C[2 * t2][3] + b0v.y, 0.f));
                uint32_t f2 = packh2(fmaxf(C[2 * t2 + 1][0] + b1v.x, 0.f),
                                     fmaxf(C[2 * t2 + 1][1] + b1v.y, 0.f));
                uint32_t f3 = packh2(fmaxf(C[2 * t2 + 1][2] + b1v.x, 0.f),
                                     fmaxf(C[2 * t2 + 1][3] + b1v.y, 0.f));
                if (nh == 0) { An[t2][0] = f0; An[t2][1] = f1; An[t2][2] = f2; An[t2][3] = f3; }
                else { A[8 + t2][0] = f0; A[8 + t2][1] = f1; A[8 + t2][2] = f2; A[8 + t2][3] = f3; }
            }
            if (nh == 1) {
                #pragma unroll
                for (int t2 = 0; t2 < 8; t2++)
                    #pragma unroll
                    for (int q = 0; q < 4; q++) A[t2][q] = An[t2][q];
            }
        } else {
            // final layer: relu(C + bias), column sums over this warp's 16 rows
            #pragma unroll
            for (int t = 0; t < 16; t++) {
                int n0 = (nh * 16 + t) * 8 + (lane & 3) * 2;
                float2 bv = __ldg((const float2*)(bias + n0));
                float u = fmaxf(C[t][0] + bv.x, 0.f) + fmaxf(C[t][2] + bv.x, 0.f);
                float v = fmaxf(C[t][1] + bv.y, 0.f) + fmaxf(C[t][3] + bv.y, 0.f);
                #pragma unroll
                for (int m = 4; m <= 16; m <<= 1) {
                    u += __shfl_xor_sync(0xffffffffu, u, m);
                    v += __shfl_xor_sync(0xffffffffu, v, m);
                }
                if (lane < 4) {
                    red[wid * HID + n0] = u;
                    red[wid * HID + n0 + 1] = v;
                }
            }
        }
        __syncthreads();
    }

    // cross-warp reduce (4 warps per i) -> g_partial
    for (int task = tid; task < 512; task += 256) {
        int il = task >> 8, col = task & 255;
        float s = red[(il * 4 + 0) * HID + col] + red[(il * 4 + 1) * HID + col]
                + red[(il * 4 + 2) * HID + col] + red[(il * 4 + 3) * HID + col];
        g_partial[((size_t)b * NOBJ + ti * 2 + il) * HID + col] = s;
    }
}

// ---------------------------------------------------------------------------
// Finish: reduce partials over i, f-MLP, log_softmax. One CTA per batch.
// ---------------------------------------------------------------------------
__global__ void finish_kernel(const float* __restrict__ f1w, const float* __restrict__ f1b,
                              const float* __restrict__ f2w, const float* __restrict__ f2b,
                              const float* __restrict__ f3w, const float* __restrict__ f3b,
                              float* __restrict__ out)
{
    __shared__ float s0[HID], s1[HID], s2[HID];
    __shared__ float sl[NOUT];
    __shared__ float sred[2];
    int b = blockIdx.x, tid = threadIdx.x;

    float s = 0.f;
    const float* pp = g_partial + (size_t)b * NOBJ * HID + tid;
    for (int i2 = 0; i2 < NOBJ; i2++) s += pp[i2 * HID];
    s0[tid] = s;
    __syncthreads();

    float a = f1b[tid];
    for (int k = 0; k < HID; k++) a += s0[k] * f1w[k * HID + tid];
    s1[tid] = fmaxf(a, 0.f);
    __syncthreads();

    a = f2b[tid];
    for (int k = 0; k < HID; k++) a += s1[k] * f2w[k * HID + tid];
    s2[tid] = fmaxf(a, 0.f);
    __syncthreads();

    if (tid < NOUT) {
        float l = f3b[tid];
        for (int k = 0; k < HID; k++) l += s2[k] * f3w[k * NOUT + tid];
        sl[tid] = l;
    }
    __syncthreads();
    if (tid == 0) {
        float m = sl[0];
        for (int o = 1; o < NOUT; o++) m = fmaxf(m, sl[o]);
        float se = 0.f;
        for (int o = 0; o < NOUT; o++) se += expf(sl[o] - m);
        sred[0] = m;
        sred[1] = logf(se);
    }
    __syncthreads();
    if (tid < NOUT) out[b * NOUT + tid] = sl[tid] - sred[0] - sred[1];
}

// ---------------------------------------------------------------------------
extern "C" void kernel_launch(void* const* d_in, const int* in_sizes, int n_in,
                              void* d_out, int out_size)
{
    const float* x   = (const float*)d_in[0];
    const float* qst = (const float*)d_in[1];
    const float* g1w = (const float*)d_in[2];
    const float* g1b = (const float*)d_in[3];
    const float* g2w = (const float*)d_in[4];
    const float* g2b = (const float*)d_in[5];
    const float* g3w = (const float*)d_in[6];
    const float* g3b = (const float*)d_in[7];
    const float* g4w = (const float*)d_in[8];
    const float* g4b = (const float*)d_in[9];
    const float* f1w = (const float*)d_in[10];
    const float* f1b = (const float*)d_in[11];
    const float* f2w = (const float*)d_in[12];
    const float* f2b = (const float*)d_in[13];
    const float* f3w = (const float*)d_in[14];
    const float* f3b = (const float*)d_in[15];
    float* out = (float*)d_out;

    cudaFuncSetAttribute(rn_mma_kernel, cudaFuncAttributeMaxDynamicSharedMemorySize, SMEM_BYTES);

    prep_kernel<<<BATCH, 256>>>(x, qst, g1w, g1b);
    weight_prep<<<dim3(HID, 3), HID>>>(g2w, g3w, g4w);
    rn_mma_kernel<<<dim3(NOBJ / 2, BATCH), 256, SMEM_BYTES>>>(g2b, g3b, g4b);
    finish_kernel<<<BATCH, 256>>>(f1w, f1b, f2w, f2b, f3w, f3b, out);
}

// round 5
// speedup vs baseline: 4.9130x; 1.5125x over previous
#include <cuda_runtime.h>
#include <cuda_fp16.h>
#include <cstdint>

#define BATCH 64
#define NOBJ 64
#define HID 256
#define NOUT 28
#define QD 128

// ---------------------------------------------------------------------------
// Device scratch (allocation-free rule: __device__ globals)
// ---------------------------------------------------------------------------
__device__ float g_Abuf[BATCH * NOBJ * HID];     // xf @ g1_w[0:26]
__device__ float g_Bbuf[BATCH * NOBJ * HID];     // xf @ g1_w[26:52] + qst @ g1_w[52:180] + g1_b
__device__ float g_partial[BATCH * NOBJ * HID];  // sum_j h4 for each (b, i)
__device__ __half g_Wfrag[3 * HID * HID];        // g2/g3/g4 weights, mma-fragment order fp16

// ---------------------------------------------------------------------------
// Helpers
// ---------------------------------------------------------------------------
__device__ __forceinline__ uint32_t smem_u32(const void* p) {
    return (uint32_t)__cvta_generic_to_shared(p);
}
__device__ __forceinline__ void cp_async16(void* dst, const void* src) {
    unsigned d = (unsigned)__cvta_generic_to_shared(dst);
    asm volatile("cp.async.cg.shared.global [%0], [%1], 16;" :: "r"(d), "l"(src));
}
__device__ __forceinline__ void cp_commit() { asm volatile("cp.async.commit_group;"); }
#define CP_WAIT(N) asm volatile("cp.async.wait_group %0;" :: "n"(N) : "memory")

__device__ __forceinline__ void mma16816(float c[4], const uint32_t a[4],
                                         uint32_t b0, uint32_t b1) {
    asm volatile(
        "mma.sync.aligned.m16n8k16.row.col.f32.f16.f16.f32 "
        "{%0,%1,%2,%3}, {%4,%5,%6,%7}, {%8,%9}, {%0,%1,%2,%3};"
        : "+f"(c[0]), "+f"(c[1]), "+f"(c[2]), "+f"(c[3])
        : "r"(a[0]), "r"(a[1]), "r"(a[2]), "r"(a[3]), "r"(b0), "r"(b1));
}
__device__ __forceinline__ void lds64(uint32_t& r0, uint32_t& r1, uint32_t addr) {
    asm volatile("ld.shared.v2.b32 {%0,%1}, [%2];" : "=r"(r0), "=r"(r1) : "r"(addr));
}
__device__ __forceinline__ uint32_t packh2(float x, float y) {
    __half2 h = __floats2half2_rn(x, y);
    return *(uint32_t*)&h;
}

// ---------------------------------------------------------------------------
// Prep: split first g-layer (rank structure of the pair concat).
// ---------------------------------------------------------------------------
__global__ void prep_kernel(const float* __restrict__ x, const float* __restrict__ qst,
                            const float* __restrict__ g1w, const float* __restrict__ g1b)
{
    __shared__ float sxf[NOBJ * 26];
    __shared__ float sq[QD];
    int b = blockIdx.x, tid = threadIdx.x;

    for (int t = tid; t < NOBJ * 26; t += 256) {
        int j = t / 26, c = t % 26;
        float v;
        if (c < 24)       v = x[(b * 24 + c) * 64 + j];
        else if (c == 24) v = ((float)j * 0.125f - 4.0f) * 0.25f;
        else              v = ((float)(j & 7) - 4.0f) * 0.25f;
        sxf[t] = v;
    }
    if (tid < QD) sq[tid] = qst[b * QD + tid];
    __syncthreads();

    int h = tid;
    float qdot = g1b[h];
    #pragma unroll 4
    for (int c = 0; c < QD; c++) qdot += sq[c] * g1w[(52 + c) * HID + h];

    for (int jc = 0; jc < NOBJ; jc += 8) {
        float accA[8], accB[8];
        #pragma unroll
        for (int u = 0; u < 8; u++) { accA[u] = 0.f; accB[u] = 0.f; }
        for (int c = 0; c < 26; c++) {
            float wA = g1w[c * HID + h];
            float wB = g1w[(26 + c) * HID + h];
            #pragma unroll
            for (int u = 0; u < 8; u++) {
                float xv = sxf[(jc + u) * 26 + c];
                accA[u] += xv * wA;
                accB[u] += xv * wB;
            }
        }
        #pragma unroll
        for (int u = 0; u < 8; u++) {
            g_Abuf[((size_t)b * NOBJ + jc + u) * HID + h] = accA[u];
            g_Bbuf[((size_t)b * NOBJ + jc + u) * HID + h] = accB[u] + qdot;
        }
    }
}

// ---------------------------------------------------------------------------
// Weight prep: W[k][n] row-major fp32 -> fragment-order fp16.
// Layout: [layer][nh(2)][kc(16)][ntl(16)][lane(32)][e(4)] halves.
// ---------------------------------------------------------------------------
__global__ void weight_prep(const float* __restrict__ w2, const float* __restrict__ w3,
                            const float* __restrict__ w4)
{
    int l = blockIdx.y;
    const float* w = (l == 0) ? w2 : (l == 1 ? w3 : w4);
    int k = blockIdx.x;     // 0..255
    int n = threadIdx.x;    // 0..255
    int kc = k >> 4, kr = k & 15;
    int nh = n >> 7, ntl = (n >> 3) & 15;
    int lane = ((n & 7) << 2) | ((kr & 7) >> 1);
    int e = (kr & 1) + ((kr >> 3) << 1);
    size_t dest = ((((size_t)(l * 2 + nh) * 16 + kc) * 16 + ntl) * 32 + lane) * 4 + e;
    g_Wfrag[dest] = __float2half(w[k * HID + n]);
}

// ---------------------------------------------------------------------------
// Main: fused g2..g4 via mma.sync (HMMA fp16, fp32 accum).
// CTA: 256 thr / 8 warps, M=128 rows (= 2 i-values x 64 j), N=256, K=256.
// Warp w owns rows 16w..16w+15; activations live in registers (C->A identity).
// Weights stream through 2 x 64KB smem ring (6 chunks = 3 layers x 2 N-halves).
// Inner loop: depth-4 register prefetch of B fragments to hide LDS latency.
// ---------------------------------------------------------------------------
#define CHUNK_BYTES 65536
#define RED_OFF (2 * CHUNK_BYTES)
#define SMEM_BYTES (RED_OFF + 8 * HID * 4)   // 131072 + 8192 = 139264

__device__ __forceinline__ void prefetch_chunk(char* smem, int c, int tid) {
    const float4* src = (const float4*)((const char*)g_Wfrag + (size_t)c * CHUNK_BYTES);
    float4* dst = (float4*)(smem + (c & 1) * CHUNK_BYTES);
    #pragma unroll
    for (int q = 0; q < 16; q++) cp_async16(dst + tid + 256 * q, src + tid + 256 * q);
}

__global__ __launch_bounds__(256, 1)
void rn_mma_kernel(const float* __restrict__ g2b_, const float* __restrict__ g3b_,
                   const float* __restrict__ g4b_)
{
    extern __shared__ char smem[];
    uint32_t sbase = smem_u32(smem);
    float* red = (float*)(smem + RED_OFF);
    int tid = threadIdx.x, wid = tid >> 5, lane = tid & 31;
    int ti = blockIdx.x, b = blockIdx.y;

    prefetch_chunk(smem, 0, tid);
    cp_commit();

    // ---- Layer-1 A fragments: h1 = relu(Abuf[j] + Bbuf[i]) ----
    uint32_t A[16][4];
    {
        int r = (wid << 4) + (lane >> 2);     // 0..127
        int j = r & 63, il = r >> 6;
        const float* A0 = g_Abuf + ((size_t)b * NOBJ + j) * HID;
        const float* Br = g_Bbuf + ((size_t)b * NOBJ + ti * 2 + il) * HID;
        #pragma unroll
        for (int kc = 0; kc < 16; kc++) {
            int k0 = kc * 16 + (lane & 3) * 2;
            #pragma unroll
            for (int hh = 0; hh < 2; hh++) {
                float2 bb = *(const float2*)(Br + k0 + 8 * hh);
                float2 a0 = *(const float2*)(A0 + k0 + 8 * hh);
                float2 a1 = *(const float2*)(A0 + 8 * HID + k0 + 8 * hh);
                A[kc][2 * hh]     = packh2(fmaxf(a0.x + bb.x, 0.f), fmaxf(a0.y + bb.y, 0.f));
                A[kc][2 * hh + 1] = packh2(fmaxf(a1.x + bb.x, 0.f), fmaxf(a1.y + bb.y, 0.f));
            }
        }
    }

    uint32_t An[8][4];   // pending new-A for nh=0 half

    for (int c = 0; c < 6; c++) {
        int l = c >> 1, nh = c & 1;
        if (c < 5) { prefetch_chunk(smem, c + 1, tid); cp_commit(); CP_WAIT(1); }
        else       { CP_WAIT(0); }
        __syncthreads();

        uint32_t wbase = sbase + (uint32_t)(c & 1) * CHUNK_BYTES + lane * 8;

        float C[16][4];
        #pragma unroll
        for (int t = 0; t < 16; t++)
            #pragma unroll
            for (int q = 0; q < 4; q++) C[t][q] = 0.f;

        // depth-4 rotating B prefetch (iter = kc*16 + t, stride 256B)
        uint32_t pb[4][2];
        #pragma unroll
        for (int p = 0; p < 4; p++) lds64(pb[p][0], pb[p][1], wbase + p * 256);

        #pragma unroll 1
        for (int kc = 0; kc < 16; kc++) {
            #pragma unroll
            for (int t = 0; t < 16; t++) {
                const int slot = t & 3;               // (kc*16+t) & 3 == t & 3
                uint32_t b0 = pb[slot][0], b1 = pb[slot][1];
                // prefetch iter+4 (tail overreads <=1KB into the other buffer: harmless)
                lds64(pb[slot][0], pb[slot][1], wbase + (kc * 16 + t + 4) * 256);
                mma16816(C[t], A[kc], b0, b1);
            }
        }

        const float* bias = (l == 0) ? g2b_ : ((l == 1) ? g3b_ : g4b_);
        if (l < 2) {
            // relu(C + bias) -> fp16 fragments for next layer (C->A layout identity)
            #pragma unroll
            for (int t2 = 0; t2 < 8; t2++) {
                int n0 = (nh * 16 + 2 * t2) * 8 + (lane & 3) * 2;
                float2 b0v = __ldg((const float2*)(bias + n0));
                float2 b1v = __ldg((const float2*)(bias + n0 + 8));
                uint32_t f0 = packh2(fmaxf(C[2 * t2][0] + b0v.x, 0.f),
                                     fmaxf(C[2 * t2][1] + b0v.y, 0.f));
                uint32_t f1 = packh2(fmaxf(C[2 * t2][2] + b0v.x, 0.f),
                                     fmaxf(C[2 * t2][3] + b0v.y, 0.f));
                uint32_t f2 = packh2(fmaxf(C[2 * t2 + 1][0] + b1v.x, 0.f),
                                     fmaxf(C[2 * t2 + 1][1] + b1v.y, 0.f));
                uint32_t f3 = packh2(fmaxf(C[2 * t2 + 1][2] + b1v.x, 0.f),
                                     fmaxf(C[2 * t2 + 1][3] + b1v.y, 0.f));
                if (nh == 0) { An[t2][0] = f0; An[t2][1] = f1; An[t2][2] = f2; An[t2][3] = f3; }
                else { A[8 + t2][0] = f0; A[8 + t2][1] = f1; A[8 + t2][2] = f2; A[8 + t2][3] = f3; }
            }
            if (nh == 1) {
                #pragma unroll
                for (int t2 = 0; t2 < 8; t2++)
                    #pragma unroll
                    for (int q = 0; q < 4; q++) A[t2][q] = An[t2][q];
            }
        } else {
            // final layer: relu(C + bias), column sums over this warp's 16 rows
            #pragma unroll
            for (int t = 0; t < 16; t++) {
                int n0 = (nh * 16 + t) * 8 + (lane & 3) * 2;
                float2 bv = __ldg((const float2*)(bias + n0));
                float u = fmaxf(C[t][0] + bv.x, 0.f) + fmaxf(C[t][2] + bv.x, 0.f);
                float v = fmaxf(C[t][1] + bv.y, 0.f) + fmaxf(C[t][3] + bv.y, 0.f);
                #pragma unroll
                for (int m = 4; m <= 16; m <<= 1) {
                    u += __shfl_xor_sync(0xffffffffu, u, m);
                    v += __shfl_xor_sync(0xffffffffu, v, m);
                }
                if (lane < 4) {
                    red[wid * HID + n0] = u;
                    red[wid * HID + n0 + 1] = v;
                }
            }
        }
        __syncthreads();
    }

    // cross-warp reduce (4 warps per i) -> g_partial
    for (int task = tid; task < 512; task += 256) {
        int il = task >> 8, col = task & 255;
        float s = red[(il * 4 + 0) * HID + col] + red[(il * 4 + 1) * HID + col]
                + red[(il * 4 + 2) * HID + col] + red[(il * 4 + 3) * HID + col];
        g_partial[((size_t)b * NOBJ + ti * 2 + il) * HID + col] = s;
    }
}

// ---------------------------------------------------------------------------
// Finish: reduce partials over i, f-MLP, log_softmax. One CTA per batch.
// Multi-accumulator unrolled dots for MLP (was latency-bound at 40us).
// ---------------------------------------------------------------------------
__global__ void finish_kernel(const float* __restrict__ f1w, const float* __restrict__ f1b,
                              const float* __restrict__ f2w, const float* __restrict__ f2b,
                              const float* __restrict__ f3w, const float* __restrict__ f3b,
                              float* __restrict__ out)
{
    __shared__ float s0[HID], s1[HID], s2[HID];
    __shared__ float sl[NOUT];
    __shared__ float sred[2];
    int b = blockIdx.x, tid = threadIdx.x;

    {
        float a0 = 0.f, a1 = 0.f, a2 = 0.f, a3 = 0.f;
        const float* pp = g_partial + (size_t)b * NOBJ * HID + tid;
        #pragma unroll
        for (int i2 = 0; i2 < NOBJ; i2 += 4) {
            a0 += pp[(i2 + 0) * HID];
            a1 += pp[(i2 + 1) * HID];
            a2 += pp[(i2 + 2) * HID];
            a3 += pp[(i2 + 3) * HID];
        }
        s0[tid] = (a0 + a1) + (a2 + a3);
    }
    __syncthreads();

    {
        float a0 = f1b[tid], a1 = 0.f, a2 = 0.f, a3 = 0.f;
        #pragma unroll 4
        for (int k = 0; k < HID; k += 4) {
            a0 += s0[k + 0] * __ldg(f1w + (k + 0) * HID + tid);
            a1 += s0[k + 1] * __ldg(f1w + (k + 1) * HID + tid);
            a2 += s0[k + 2] * __ldg(f1w + (k + 2) * HID + tid);
            a3 += s0[k + 3] * __ldg(f1w + (k + 3) * HID + tid);
        }
        s1[tid] = fmaxf((a0 + a1) + (a2 + a3), 0.f);
    }
    __syncthreads();

    {
        float a0 = f2b[tid], a1 = 0.f, a2 = 0.f, a3 = 0.f;
        #pragma unroll 4
        for (int k = 0; k < HID; k += 4) {
            a0 += s1[k + 0] * __ldg(f2w + (k + 0) * HID + tid);
            a1 += s1[k + 1] * __ldg(f2w + (k + 1) * HID + tid);
            a2 += s1[k + 2] * __ldg(f2w + (k + 2) * HID + tid);
            a3 += s1[k + 3] * __ldg(f2w + (k + 3) * HID + tid);
        }
        s2[tid] = fmaxf((a0 + a1) + (a2 + a3), 0.f);
    }
    __syncthreads();

    if (tid < NOUT) {
        float a0 = f3b[tid], a1 = 0.f, a2 = 0.f, a3 = 0.f;
        #pragma unroll 4
        for (int k = 0; k < HID; k += 4) {
            a0 += s2[k + 0] * __ldg(f3w + (k + 0) * NOUT + tid);
            a1 += s2[k + 1] * __ldg(f3w + (k + 1) * NOUT + tid);
            a2 += s2[k + 2] * __ldg(f3w + (k + 2) * NOUT + tid);
            a3 += s2[k + 3] * __ldg(f3w + (k + 3) * NOUT + tid);
        }
        sl[tid] = (a0 + a1) + (a2 + a3);
    }
    __syncthreads();
    if (tid == 0) {
        float m = sl[0];
        for (int o = 1; o < NOUT; o++) m = fmaxf(m, sl[o]);
        float se = 0.f;
        for (int o = 0; o < NOUT; o++) se += expf(sl[o] - m);
        sred[0] = m;
        sred[1] = logf(se);
    }
    __syncthreads();
    if (tid < NOUT) out[b * NOUT + tid] = sl[tid] - sred[0] - sred[1];
}

// ---------------------------------------------------------------------------
extern "C" void kernel_launch(void* const* d_in, const int* in_sizes, int n_in,
                              void* d_out, int out_size)
{
    const float* x   = (const float*)d_in[0];
    const float* qst = (const float*)d_in[1];
    const float* g1w = (const float*)d_in[2];
    const float* g1b = (const float*)d_in[3];
    const float* g2w = (const float*)d_in[4];
    const float* g2b = (const float*)d_in[5];
    const float* g3w = (const float*)d_in[6];
    const float* g3b = (const float*)d_in[7];
    const float* g4w = (const float*)d_in[8];
    const float* g4b = (const float*)d_in[9];
    const float* f1w = (const float*)d_in[10];
    const float* f1b = (const float*)d_in[11];
    const float* f2w = (const float*)d_in[12];
    const float* f2b = (const float*)d_in[13];
    const float* f3w = (const float*)d_in[14];
    const float* f3b = (const float*)d_in[15];
    float* out = (float*)d_out;

    cudaFuncSetAttribute(rn_mma_kernel, cudaFuncAttributeMaxDynamicSharedMemorySize, SMEM_BYTES);

    prep_kernel<<<BATCH, 256>>>(x, qst, g1w, g1b);
    weight_prep<<<dim3(HID, 3), HID>>>(g2w, g3w, g4w);
    rn_mma_kernel<<<dim3(NOBJ / 2, BATCH), 256, SMEM_BYTES>>>(g2b, g3b, g4b);
    finish_kernel<<<BATCH, 256>>>(f1w, f1b, f2w, f2b, f3w, f3b, out);
}

// round 8
// speedup vs baseline: 6.2957x; 1.2814x over previous
#include <cuda_runtime.h>
#include <cuda_fp16.h>
#include <cstdint>

#define BATCH 64
#define NOBJ 64
#define HID 256
#define NOUT 28
#define QD 128

// ---------------------------------------------------------------------------
// Device scratch (allocation-free rule: __device__ globals)
// ---------------------------------------------------------------------------
__device__ float g_Abuf[BATCH * NOBJ * HID];     // xf @ g1_w[0:26]
__device__ float g_Bbuf[BATCH * NOBJ * HID];     // xf @ g1_w[26:52] + qst @ g1_w[52:180] + g1_b
__device__ float g_partial[BATCH * NOBJ * HID];  // sum_j h4 for each (b, i)
__device__ __half g_Wfrag[3 * HID * HID];        // g2/g3/g4 weights, fragment order fp16

// ---------------------------------------------------------------------------
// Helpers
// ---------------------------------------------------------------------------
__device__ __forceinline__ uint32_t smem_u32(const void* p) {
    return (uint32_t)__cvta_generic_to_shared(p);
}
__device__ __forceinline__ void cp_async16(void* dst, const void* src) {
    unsigned d = (unsigned)__cvta_generic_to_shared(dst);
    asm volatile("cp.async.cg.shared.global [%0], [%1], 16;" :: "r"(d), "l"(src));
}
__device__ __forceinline__ void cp_commit() { asm volatile("cp.async.commit_group;"); }
#define CP_WAIT(N) asm volatile("cp.async.wait_group %0;" :: "n"(N) : "memory")

__device__ __forceinline__ void mma16816(float c[4], const uint32_t a[4],
                                         uint32_t b0, uint32_t b1) {
    asm volatile(
        "mma.sync.aligned.m16n8k16.row.col.f32.f16.f16.f32 "
        "{%0,%1,%2,%3}, {%4,%5,%6,%7}, {%8,%9}, {%0,%1,%2,%3};"
        : "+f"(c[0]), "+f"(c[1]), "+f"(c[2]), "+f"(c[3])
        : "r"(a[0]), "r"(a[1]), "r"(a[2]), "r"(a[3]), "r"(b0), "r"(b1));
}
__device__ __forceinline__ void lds64(uint32_t& r0, uint32_t& r1, uint32_t addr) {
    asm volatile("ld.shared.v2.b32 {%0,%1}, [%2];" : "=r"(r0), "=r"(r1) : "r"(addr));
}
__device__ __forceinline__ uint32_t packh2(float x, float y) {
    __half2 h = __floats2half2_rn(x, y);
    return *(uint32_t*)&h;
}

// ---------------------------------------------------------------------------
// Prep: split first g-layer (rank structure of the pair concat).
// ---------------------------------------------------------------------------
__global__ void prep_kernel(const float* __restrict__ x, const float* __restrict__ qst,
                            const float* __restrict__ g1w, const float* __restrict__ g1b)
{
    __shared__ float sxf[NOBJ * 26];
    __shared__ float sq[QD];
    int b = blockIdx.x, tid = threadIdx.x;

    for (int t = tid; t < NOBJ * 26; t += 256) {
        int j = t / 26, c = t % 26;
        float v;
        if (c < 24)       v = x[(b * 24 + c) * 64 + j];
        else if (c == 24) v = ((float)j * 0.125f - 4.0f) * 0.25f;
        else              v = ((float)(j & 7) - 4.0f) * 0.25f;
        sxf[t] = v;
    }
    if (tid < QD) sq[tid] = qst[b * QD + tid];
    __syncthreads();

    int h = tid;
    float qdot = g1b[h];
    #pragma unroll 4
    for (int c = 0; c < QD; c++) qdot += sq[c] * g1w[(52 + c) * HID + h];

    for (int jc = 0; jc < NOBJ; jc += 8) {
        float accA[8], accB[8];
        #pragma unroll
        for (int u = 0; u < 8; u++) { accA[u] = 0.f; accB[u] = 0.f; }
        for (int c = 0; c < 26; c++) {
            float wA = g1w[c * HID + h];
            float wB = g1w[(26 + c) * HID + h];
            #pragma unroll
            for (int u = 0; u < 8; u++) {
                float xv = sxf[(jc + u) * 26 + c];
                accA[u] += xv * wA;
                accB[u] += xv * wB;
            }
        }
        #pragma unroll
        for (int u = 0; u < 8; u++) {
            g_Abuf[((size_t)b * NOBJ + jc + u) * HID + h] = accA[u];
            g_Bbuf[((size_t)b * NOBJ + jc + u) * HID + h] = accB[u] + qdot;
        }
    }
}

// ---------------------------------------------------------------------------
// Weight prep: W[k][n] row-major fp32 -> fragment-order fp16.
// Chunk = (layer, n-quarter): [l(3)][q(4)][kc(16)][ntl(8)][lane(32)][e(4)]
// ---------------------------------------------------------------------------
__global__ void weight_prep(const float* __restrict__ w2, const float* __restrict__ w3,
                            const float* __restrict__ w4)
{
    int l = blockIdx.y;
    const float* w = (l == 0) ? w2 : (l == 1 ? w3 : w4);
    int k = blockIdx.x;     // 0..255
    int n = threadIdx.x;    // 0..255
    int kc = k >> 4, kr = k & 15;
    int q = n >> 6, ntl = (n >> 3) & 7;
    int lane = ((n & 7) << 2) | ((kr & 7) >> 1);
    int e = (kr & 1) + ((kr >> 3) << 1);
    size_t dest = (((((size_t)(l * 4 + q) * 16 + kc) * 8 + ntl) * 32 + lane)) * 4 + e;
    g_Wfrag[dest] = __float2half(w[k * HID + n]);
}

// ---------------------------------------------------------------------------
// Main: fused g2..g4 via mma.sync, m32 warps (2 MMAs per B fragment load).
// CTA: 256 thr / 8 warps; M=256 rows (= 4 i-values x 64 j); warp owns m32.
// N processed in quarters (64 cols); K=256. 24 chunks of 32KB, 2-deep ring.
// Next-layer A fragments parked in per-thread smem slabs (reg pressure valve).
// ---------------------------------------------------------------------------
#define CHUNK_BYTES 32768
#define STAG_OFF (2 * CHUNK_BYTES)           // 65536
#define RED_OFF (STAG_OFF + 131072)          // 196608
#define SMEM_BYTES (RED_OFF + 8 * HID * 4)   // 204800

__device__ __forceinline__ void prefetch_chunk(char* smem, int c, int tid) {
    const float4* src = (const float4*)((const char*)g_Wfrag + (size_t)c * CHUNK_BYTES);
    float4* dst = (float4*)(smem + (c & 1) * CHUNK_BYTES);
    #pragma unroll
    for (int q = 0; q < 8; q++) cp_async16(dst + tid + 256 * q, src + tid + 256 * q);
}

__global__ __launch_bounds__(256, 1)
void rn_mma_kernel(const float* __restrict__ g2b_, const float* __restrict__ g3b_,
                   const float* __restrict__ g4b_)
{
    extern __shared__ char smem[];
    uint32_t sbase = smem_u32(smem);
    char* stag = smem + STAG_OFF;
    float* red = (float*)(smem + RED_OFF);
    int tid = threadIdx.x, wid = tid >> 5, lane = tid & 31;
    int ti = blockIdx.x, b = blockIdx.y;

    prefetch_chunk(smem, 0, tid);
    cp_commit();

    // ---- Layer-1 A fragments (m32 = two m16 halves): h1 = relu(Abuf[j]+Bbuf[i]) ----
    uint32_t A[2][16][4];
    {
        int i = ti * 4 + (wid >> 1);
        const float* Br = g_Bbuf + ((size_t)b * NOBJ + i) * HID;
        #pragma unroll
        for (int mh = 0; mh < 2; mh++) {
            int j0 = ((wid * 32 + mh * 16) & 63) + (lane >> 2);
            const float* A0 = g_Abuf + ((size_t)b * NOBJ + j0) * HID;
            #pragma unroll
            for (int kc = 0; kc < 16; kc++) {
                int k0 = kc * 16 + (lane & 3) * 2;
                #pragma unroll
                for (int hh = 0; hh < 2; hh++) {
                    float2 bb = *(const float2*)(Br + k0 + 8 * hh);
                    float2 a0 = *(const float2*)(A0 + k0 + 8 * hh);
                    float2 a1 = *(const float2*)(A0 + 8 * HID + k0 + 8 * hh);
                    A[mh][kc][2 * hh]     = packh2(fmaxf(a0.x + bb.x, 0.f), fmaxf(a0.y + bb.y, 0.f));
                    A[mh][kc][2 * hh + 1] = packh2(fmaxf(a1.x + bb.x, 0.f), fmaxf(a1.y + bb.y, 0.f));
                }
            }
        }
    }

    #pragma unroll 1
    for (int c = 0; c < 12; c++) {
        int l = c >> 2, q = c & 3;
        if (c < 11) { prefetch_chunk(smem, c + 1, tid); cp_commit(); CP_WAIT(1); }
        else        { CP_WAIT(0); }
        __syncthreads();

        uint32_t wbase = sbase + (uint32_t)(c & 1) * CHUNK_BYTES + lane * 8;

        float C[2][8][4];
        #pragma unroll
        for (int mh = 0; mh < 2; mh++)
            #pragma unroll
            for (int t = 0; t < 8; t++)
                #pragma unroll
                for (int e = 0; e < 4; e++) C[mh][t][e] = 0.f;

        // depth-4 rotating B prefetch; iter = kc*8 + t, stride 256B
        uint32_t pb[4][2];
        #pragma unroll
        for (int p = 0; p < 4; p++) lds64(pb[p][0], pb[p][1], wbase + p * 256);

        #pragma unroll
        for (int kc = 0; kc < 16; kc++) {
            #pragma unroll
            for (int t = 0; t < 8; t++) {
                const int slot = t & 3;
                uint32_t b0 = pb[slot][0], b1 = pb[slot][1];
                // prefetch iter+4 (tail overreads into staging region: discarded)
                lds64(pb[slot][0], pb[slot][1], wbase + (kc * 8 + t + 4) * 256);
                mma16816(C[0][t], A[0][kc], b0, b1);
                mma16816(C[1][t], A[1][kc], b0, b1);
            }
        }

        const float* bias = (l == 0) ? g2b_ : ((l == 1) ? g3b_ : g4b_);
        if (l < 2) {
            // relu(C+bias) -> packed next-A fragments, parked in smem slabs
            #pragma unroll
            for (int mh = 0; mh < 2; mh++)
                #pragma unroll
                for (int t2 = 0; t2 < 4; t2++) {
                    int n0 = (q * 8 + 2 * t2) * 8 + (lane & 3) * 2;
                    float2 b0v = __ldg((const float2*)(bias + n0));
                    float2 b1v = __ldg((const float2*)(bias + n0 + 8));
                    uint4 f;
                    f.x = packh2(fmaxf(C[mh][2 * t2][0] + b0v.x, 0.f),
                                 fmaxf(C[mh][2 * t2][1] + b0v.y, 0.f));
                    f.y = packh2(fmaxf(C[mh][2 * t2][2] + b0v.x, 0.f),
                                 fmaxf(C[mh][2 * t2][3] + b0v.y, 0.f));
                    f.z = packh2(fmaxf(C[mh][2 * t2 + 1][0] + b1v.x, 0.f),
                                 fmaxf(C[mh][2 * t2 + 1][1] + b1v.y, 0.f));
                    f.w = packh2(fmaxf(C[mh][2 * t2 + 1][2] + b1v.x, 0.f),
                                 fmaxf(C[mh][2 * t2 + 1][3] + b1v.y, 0.f));
                    int kcp = q * 4 + t2;
                    *(uint4*)(stag + (((mh * 16 + kcp) << 12) | (tid << 4))) = f;
                }
            if (q == 3) {
                // layer complete: reload all A fragments (per-thread private)
                #pragma unroll
                for (int mh = 0; mh < 2; mh++)
                    #pragma unroll
                    for (int kk = 0; kk < 16; kk++) {
                        uint4 v = *(const uint4*)(stag + (((mh * 16 + kk) << 12) | (tid << 4)));
                        A[mh][kk][0] = v.x; A[mh][kk][1] = v.y;
                        A[mh][kk][2] = v.z; A[mh][kk][3] = v.w;
                    }
            }
        } else {
            // final layer: relu(C+bias), column sums over warp's 32 rows
            #pragma unroll
            for (int t = 0; t < 8; t++) {
                int n0 = (q * 8 + t) * 8 + (lane & 3) * 2;
                float2 bv = __ldg((const float2*)(bias + n0));
                float u = fmaxf(C[0][t][0] + bv.x, 0.f) + fmaxf(C[0][t][2] + bv.x, 0.f)
                        + fmaxf(C[1][t][0] + bv.x, 0.f) + fmaxf(C[1][t][2] + bv.x, 0.f);
                float v = fmaxf(C[0][t][1] + bv.y, 0.f) + fmaxf(C[0][t][3] + bv.y, 0.f)
                        + fmaxf(C[1][t][1] + bv.y, 0.f) + fmaxf(C[1][t][3] + bv.y, 0.f);
                #pragma unroll
                for (int m = 4; m <= 16; m <<= 1) {
                    u += __shfl_xor_sync(0xffffffffu, u, m);
                    v += __shfl_xor_sync(0xffffffffu, v, m);
                }
                if (lane < 4) {
                    red[wid * HID + n0] = u;
                    red[wid * HID + n0 + 1] = v;
                }
            }
        }
        __syncthreads();
    }

    // cross-warp reduce (2 warps per i) -> g_partial
    for (int task = tid; task < 1024; task += 256) {
        int il = task >> 8, col = task & 255;
        float s = red[(il * 2) * HID + col] + red[(il * 2 + 1) * HID + col];
        g_partial[((size_t)b * NOBJ + ti * 4 + il) * HID + col] = s;
    }
}

// ---------------------------------------------------------------------------
// Finish: reduce partials over i, f-MLP, log_softmax. 512 threads, split-K.
// ---------------------------------------------------------------------------
__global__ __launch_bounds__(512)
void finish_kernel(const float* __restrict__ f1w, const float* __restrict__ f1b,
                   const float* __restrict__ f2w, const float* __restrict__ f2b,
                   const float* __restrict__ f3w, const float* __restrict__ f3b,
                   float* __restrict__ out)
{
    __shared__ float s0[HID], s1[HID], s2[HID];
    __shared__ float part[512];
    __shared__ float sl[NOUT];
    __shared__ float sred[2];
    int b = blockIdx.x, tid = threadIdx.x;
    int col = tid & 255, half = tid >> 8;

    // stage 0: reduce g_partial over 64 i (each thread: 32 of them)
    {
        const float* pp = g_partial + (size_t)b * NOBJ * HID + (size_t)half * 32 * HID + col;
        float a0 = 0.f, a1 = 0.f, a2 = 0.f, a3 = 0.f;
        #pragma unroll
        for (int i2 = 0; i2 < 32; i2 += 4) {
            a0 += pp[(i2 + 0) * HID];
            a1 += pp[(i2 + 1) * HID];
            a2 += pp[(i2 + 2) * HID];
            a3 += pp[(i2 + 3) * HID];
        }
        part[tid] = (a0 + a1) + (a2 + a3);
    }
    __syncthreads();
    if (tid < HID) s0[tid] = part[tid] + part[tid + 256];
    __syncthreads();

    // layer f1
    {
        const float* wcol = f1w + (size_t)half * 128 * HID + col;
        float a0 = 0.f, a1 = 0.f, a2 = 0.f, a3 = 0.f;
        #pragma unroll 4
        for (int k = 0; k < 128; k += 4) {
            a0 += s0[half * 128 + k + 0] * __ldg(wcol + (k + 0) * HID);
            a1 += s0[half * 128 + k + 1] * __ldg(wcol + (k + 1) * HID);
            a2 += s0[half * 128 + k + 2] * __ldg(wcol + (k + 2) * HID);
            a3 += s0[half * 128 + k + 3] * __ldg(wcol + (k + 3) * HID);
        }
        part[tid] = (a0 + a1) + (a2 + a3);
    }
    __syncthreads();
    if (tid < HID) s1[tid] = fmaxf(part[tid] + part[tid + 256] + f1b[tid], 0.f);
    __syncthreads();

    // layer f2
    {
        const float* wcol = f2w + (size_t)half * 128 * HID + col;
        float a0 = 0.f, a1 = 0.f, a2 = 0.f, a3 = 0.f;
        #pragma unroll 4
        for (int k = 0; k < 128; k += 4) {
            a0 += s1[half * 128 + k + 0] * __ldg(wcol + (k + 0) * HID);
            a1 += s1[half * 128 + k + 1] * __ldg(wcol + (k + 1) * HID);
            a2 += s1[half * 128 + k + 2] * __ldg(wcol + (k + 2) * HID);
            a3 += s1[half * 128 + k + 3] * __ldg(wcol + (k + 3) * HID);
        }
        part[tid] = (a0 + a1) + (a2 + a3);
    }
    __syncthreads();
    if (tid < HID) s2[tid] = fmaxf(part[tid] + part[tid + 256] + f2b[tid], 0.f);
    __syncthreads();

    // layer f3: 28 outputs, 16 k-segments of 16
    {
        int o = tid >> 4, seg = tid & 15;
        float a = 0.f;
        if (o < NOUT) {
            #pragma unroll
            for (int k = 0; k < 16; k++)
                a += s2[seg * 16 + k] * __ldg(f3w + (seg * 16 + k) * NOUT + o);
        }
        part[tid] = a;
    }
    __syncthreads();
    if (tid < NOUT) {
        float a = f3b[tid];
        #pragma unroll
        for (int seg = 0; seg < 16; seg++) a += part[(tid << 4) + seg];
        sl[tid] = a;
    }
    __syncthreads();
    if (tid == 0) {
        float m = sl[0];
        for (int o = 1; o < NOUT; o++) m = fmaxf(m, sl[o]);
        float se = 0.f;
        for (int o = 0; o < NOUT; o++) se += expf(sl[o] - m);
        sred[0] = m;
        sred[1] = logf(se);
    }
    __syncthreads();
    if (tid < NOUT) out[b * NOUT + tid] = sl[tid] - sred[0] - sred[1];
}

// ---------------------------------------------------------------------------
extern "C" void kernel_launch(void* const* d_in, const int* in_sizes, int n_in,
                              void* d_out, int out_size)
{
    const float* x   = (const float*)d_in[0];
    const float* qst = (const float*)d_in[1];
    const float* g1w = (const float*)d_in[2];
    const float* g1b = (const float*)d_in[3];
    const float* g2w = (const float*)d_in[4];
    const float* g2b = (const float*)d_in[5];
    const float* g3w = (const float*)d_in[6];
    const float* g3b = (const float*)d_in[7];
    const float* g4w = (const float*)d_in[8];
    const float* g4b = (const float*)d_in[9];
    const float* f1w = (const float*)d_in[10];
    const float* f1b = (const float*)d_in[11];
    const float* f2w = (const float*)d_in[12];
    const float* f2b = (const float*)d_in[13];
    const float* f3w = (const float*)d_in[14];
    const float* f3b = (const float*)d_in[15];
    float* out = (float*)d_out;

    cudaFuncSetAttribute(rn_mma_kernel, cudaFuncAttributeMaxDynamicSharedMemorySize, SMEM_BYTES);

    prep_kernel<<<BATCH, 256>>>(x, qst, g1w, g1b);
    weight_prep<<<dim3(HID, 3), HID>>>(g2w, g3w, g4w);
    rn_mma_kernel<<<dim3(NOBJ / 4, BATCH), 256, SMEM_BYTES>>>(g2b, g3b, g4b);
    finish_kernel<<<BATCH, 512>>>(f1w, f1b, f2w, f2b, f3w, f3b, out);
}